// round 11
// baseline (speedup 1.0000x reference)
#include <cuda_runtime.h>
#include <cuda_bf16.h>
#include <cstdint>
#include <math.h>

// Problem constants
#define BGR   32768      // graphs
#define NPG   54         // nodes per graph
#define EPG   144        // directed edges per graph
#define GLOB  10
#define ACTW  240        // padded activation width (216 embeds + 10 glob + 14 pad) = 15*16
#define KCH   16         // K-chunk for K2

// Scratch: concatenated activations [BGR][ACTW]; cols 226..239 zeroed
__device__ float g_act[(size_t)BGR * ACTW];

// ---------------- f32x2 packed helpers (sm_100+) ----------------
__device__ __forceinline__ unsigned long long pk2(float x, float y) {
    unsigned long long r;
    asm("mov.b64 %0, {%1, %2};" : "=l"(r) : "f"(x), "f"(y));
    return r;
}
__device__ __forceinline__ void fma2(unsigned long long &d, unsigned long long a, unsigned long long b) {
    asm("fma.rn.f32x2 %0, %1, %2, %0;" : "+l"(d) : "l"(a), "l"(b));
}
__device__ __forceinline__ float2 upk(unsigned long long v) {
    float2 f;
    asm("mov.b64 {%0, %1}, %2;" : "=f"(f.x), "=f"(f.y) : "l"(v));
    return f;
}

// =================================================================
// K1: per-graph fused GraphConv x2 + global MLP -> g_act
// (byte-identical to R10 — isolates the K2 change)
// =================================================================
__global__ __launch_bounds__(128)
void k1_graph(const float* __restrict__ x,
              const int*   __restrict__ ei,      // [2][E]
              const float* __restrict__ ea,      // [E]
              const float* __restrict__ gf,      // [B][10]
              const float* __restrict__ W_rel1,  // [8][16]
              const float* __restrict__ b1,      // [16]
              const float* __restrict__ W_root1, // [8][16]
              const float* __restrict__ W_rel2,  // [16][4]
              const float* __restrict__ b2,      // [4]
              const float* __restrict__ W_root2, // [16][4]
              const float* __restrict__ Wg1, const float* __restrict__ bg1,
              const float* __restrict__ Wg2, const float* __restrict__ bg2,
              const float* __restrict__ Wg3, const float* __restrict__ bg3)
{
    __shared__ float4 sx4[NPG * 2];          // x rows [54][8]
    __shared__ int    s_src[EPG], s_dst[EPG];
    __shared__ float  s_attr[EPG];
    __shared__ int    s_cnt[56], s_start[56], s_rank[EPG];
    __shared__ __align__(8) float2 s_sedge[EPG];   // sorted {attr, src_as_float}
    __shared__ __align__(8) float s_yroot[NPG * 16];   // x@W_root1 + b1
    __shared__ __align__(16) float4 s_zrel[NPG];    // h1@W_rel2
    __shared__ __align__(16) float4 s_zroot[NPG];   // h1@W_root2 + b2
    __shared__ __align__(16) float  w_rel1[128], w_root1[128], b1s[16];
    __shared__ __align__(16) float  w_rel2[64],  w_root2[64], b2s[4];
    __shared__ float  swg1[80], sbg1[8], swg2[64], sbg2[8], swg3[80], sbg3[10];
    __shared__ float  s_gf[GLOB];

    const int t    = threadIdx.x;
    const int lane = t & 31;
    const int warp = t >> 5;
    const int g    = blockIdx.x;

    const long long E = (long long)BGR * EPG;

    // ---------------- Phase 0: loads (vectorized) ----------------
    if (t < NPG * 2) sx4[t] = ((const float4*)(x + (size_t)g * (NPG * 8)))[t];
    {
        const int base = g * NPG;
        if (t < 36) {                       // src: 144 ints = 36 int4
            int4 v = ((const int4*)(ei + (size_t)g * EPG))[t];
            s_src[t * 4 + 0] = v.x - base;
            s_src[t * 4 + 1] = v.y - base;
            s_src[t * 4 + 2] = v.z - base;
            s_src[t * 4 + 3] = v.w - base;
        } else if (t < 72) {                // dst
            int i = t - 36;
            int4 v = ((const int4*)(ei + E + (size_t)g * EPG))[i];
            s_dst[i * 4 + 0] = v.x - base;
            s_dst[i * 4 + 1] = v.y - base;
            s_dst[i * 4 + 2] = v.z - base;
            s_dst[i * 4 + 3] = v.w - base;
        } else if (t < 108) {               // attr
            int i = t - 72;
            float4 v = ((const float4*)(ea + (size_t)g * EPG))[i];
            s_attr[i * 4 + 0] = v.x;
            s_attr[i * 4 + 1] = v.y;
            s_attr[i * 4 + 2] = v.z;
            s_attr[i * 4 + 3] = v.w;
        }
    }
    if (t < 128) { w_rel1[t] = W_rel1[t]; w_root1[t] = W_root1[t]; }
    if (t < 16)  b1s[t] = b1[t];
    if (t < 64)  { w_rel2[t] = W_rel2[t]; w_root2[t] = W_root2[t]; }
    if (t < 4)   b2s[t] = b2[t];
    if (t < 80)  { swg1[t] = Wg1[t]; swg3[t] = Wg3[t]; }
    if (t < 64)  swg2[t] = Wg2[t];
    if (t < 8)   { sbg1[t] = bg1[t]; sbg2[t] = bg2[t]; }
    if (t < 10)  { sbg3[t] = bg3[t]; s_gf[t] = gf[(size_t)g * GLOB + t]; }
    __syncthreads();

    // ---------------- Phase 1: warp0 = CSR, warps1-2 = y_root, warp3 = MLP ----------------
    if (warp == 0) {
        for (int i = lane; i < 56; i += 32) s_cnt[i] = 0;
        __syncwarp();
        #pragma unroll
        for (int c = 0; c < 5; c++) {
            int e = c * 32 + lane;
            bool valid = (e < EPG);
            int d = valid ? s_dst[e] : 54;      // sentinel bucket (unused)
            unsigned mask = __match_any_sync(0xffffffffu, d);
            int leader = __ffs(mask) - 1;
            int rk = __popc(mask & ((1u << lane) - 1u));
            int basec = s_cnt[d];
            if (valid) s_rank[e] = basec + rk;
            __syncwarp();
            if (lane == leader) s_cnt[d] = basec + __popc(mask);
            __syncwarp();
        }
        // Warp-parallel exclusive prefix scan of s_cnt[0..53] -> s_start[0..54]
        {
            int v0 = (lane < NPG) ? s_cnt[lane] : 0;
            int v1 = (lane + 32 < NPG) ? s_cnt[lane + 32] : 0;
            int s0 = v0, s1 = v1;
            #pragma unroll
            for (int off = 1; off < 32; off <<= 1) {
                int n0 = __shfl_up_sync(0xffffffffu, s0, off);
                int n1 = __shfl_up_sync(0xffffffffu, s1, off);
                if (lane >= off) { s0 += n0; s1 += n1; }
            }
            int total0 = __shfl_sync(0xffffffffu, s0, 31);
            s_start[lane] = s0 - v0;
            if (lane + 32 <= NPG) s_start[lane + 32] = total0 + s1 - v1;
        }
        __syncwarp();
        #pragma unroll
        for (int c = 0; c < 5; c++) {
            int e = c * 32 + lane;
            if (e < EPG) {
                int slot = s_start[s_dst[e]] + s_rank[e];
                s_sedge[slot] = make_float2(s_attr[e], __int_as_float(s_src[e]));
            }
        }
    } else if (warp == 3) {
        // Global MLP 10 -> 8 -> 8 -> 10 (single warp, shuffle-broadcast)
        float g1 = 0.f;
        if (lane < 8) {
            float a = sbg1[lane];
            #pragma unroll
            for (int i = 0; i < GLOB; i++) a += s_gf[i] * swg1[i * 8 + lane];
            g1 = fmaxf(a, 0.f);
        }
        float a2 = (lane < 8) ? sbg2[lane] : 0.f;
        #pragma unroll
        for (int i = 0; i < 8; i++) {
            float v = __shfl_sync(0xffffffffu, g1, i);
            if (lane < 8) a2 += v * swg2[i * 8 + lane];
        }
        float g2 = fmaxf(a2, 0.f);
        float a3 = (lane < GLOB) ? sbg3[lane] : 0.f;
        #pragma unroll
        for (int i = 0; i < 8; i++) {
            float v = __shfl_sync(0xffffffffu, g2, i);
            if (lane < GLOB) a3 += v * swg3[i * GLOB + lane];
        }
        if (lane < GLOB) g_act[(size_t)g * ACTW + 216 + lane] = fmaxf(a3, 0.f);
        if (lane >= GLOB && lane < 24) g_act[(size_t)g * ACTW + 216 + lane] = 0.f; // pad 226..239
    } else {
        // warps 1-2: y_root[n][k-pair] = x[n] @ W_root1 + b1 (f32x2 pairs)
        int idx = (warp - 1) * 32 + lane;                 // 0..63
        for (int o = idx; o < NPG * 8; o += 64) {         // 432 float2 outputs
            int n = o >> 3, j = o & 7;                    // node, k-pair
            float4 X0 = sx4[n * 2], X1 = sx4[n * 2 + 1];
            float xf[8] = {X0.x, X0.y, X0.z, X0.w, X1.x, X1.y, X1.z, X1.w};
            unsigned long long acc = *(const unsigned long long*)(b1s + 2 * j);
            #pragma unroll
            for (int f = 0; f < 8; f++) {
                unsigned long long wd = *(const unsigned long long*)(w_root1 + f * 16 + 2 * j);
                fma2(acc, pk2(xf[f], xf[f]), wd);
            }
            *(float2*)(s_yroot + n * 16 + 2 * j) = upk(acc);
        }
    }
    __syncthreads();

    // ---------------- Phase 2: fused conv1 agg + h1 + z (register pair chain) ----------------
    if (t < NPG * 2) {
        const int n = t >> 1, half = t & 1;
        const unsigned mk = (t < 96) ? 0xffffffffu : 0x00000fffu;  // active lanes in my warp

        // (a) gather my 4 agg dims over this node's in-edges
        float4 agg = make_float4(0.f, 0.f, 0.f, 0.f);
        const int i0 = s_start[n], i1 = s_start[n + 1];
        for (int i = i0; i < i1; i++) {
            float2 e2 = s_sedge[i];
            int s = __float_as_int(e2.y);
            float w = e2.x;
            float4 xv = sx4[s * 2 + half];
            agg.x += w * xv.x; agg.y += w * xv.y; agg.z += w * xv.z; agg.w += w * xv.w;
        }

        // (b) pair-exchange -> full agg[8]
        float4 aggO;
        aggO.x = __shfl_xor_sync(mk, agg.x, 1);
        aggO.y = __shfl_xor_sync(mk, agg.y, 1);
        aggO.z = __shfl_xor_sync(mk, agg.z, 1);
        aggO.w = __shfl_xor_sync(mk, agg.w, 1);
        float a8[8];
        if (half == 0) {
            a8[0] = agg.x;  a8[1] = agg.y;  a8[2] = agg.z;  a8[3] = agg.w;
            a8[4] = aggO.x; a8[5] = aggO.y; a8[6] = aggO.z; a8[7] = aggO.w;
        } else {
            a8[0] = aggO.x; a8[1] = aggO.y; a8[2] = aggO.z; a8[3] = aggO.w;
            a8[4] = agg.x;  a8[5] = agg.y;  a8[6] = agg.z;  a8[7] = agg.w;
        }

        // (c) my 8 h1 outputs: k in [half*8, half*8+8); acc init = y_root (has b1)
        unsigned long long acc[4];
        #pragma unroll
        for (int j = 0; j < 4; j++)
            acc[j] = *(const unsigned long long*)(s_yroot + n * 16 + half * 8 + 2 * j);
        #pragma unroll
        for (int f = 0; f < 8; f++) {
            unsigned long long ad = pk2(a8[f], a8[f]);
            const ulonglong2* wr = (const ulonglong2*)(w_rel1 + f * 16 + half * 8);
            ulonglong2 w0 = wr[0], w1 = wr[1];
            fma2(acc[0], ad, w0.x); fma2(acc[1], ad, w0.y);
            fma2(acc[2], ad, w1.x); fma2(acc[3], ad, w1.y);
        }
        float h[8];
        #pragma unroll
        for (int j = 0; j < 4; j++) {
            float2 v = upk(acc[j]);
            h[2 * j]     = fmaxf(v.x, 0.f);
            h[2 * j + 1] = fmaxf(v.y, 0.f);
        }

        // (d) z partials over my k-half: z_rel = h1@W_rel2, z_root = h1@W_root2 (+b2 on half0)
        unsigned long long zr0 = 0ULL, zr1 = 0ULL, zo0, zo1;
        if (half == 0) {
            ulonglong2 bb = *(const ulonglong2*)b2s;
            zo0 = bb.x; zo1 = bb.y;
        } else { zo0 = 0ULL; zo1 = 0ULL; }
        #pragma unroll
        for (int kk = 0; kk < 8; kk++) {
            int k = half * 8 + kk;
            unsigned long long hd = pk2(h[kk], h[kk]);
            ulonglong2 wr = *(const ulonglong2*)(w_rel2 + k * 4);
            fma2(zr0, hd, wr.x); fma2(zr1, hd, wr.y);
            ulonglong2 wo = *(const ulonglong2*)(w_root2 + k * 4);
            fma2(zo0, hd, wo.x); fma2(zo1, hd, wo.y);
        }
        // (e) pair-combine and write z
        float2 a0 = upk(zr0), a1 = upk(zr1), b0 = upk(zo0), b1v = upk(zo1);
        float zb[8] = {a0.x, a0.y, a1.x, a1.y, b0.x, b0.y, b1v.x, b1v.y};
        #pragma unroll
        for (int j = 0; j < 8; j++)
            zb[j] += __shfl_xor_sync(mk, zb[j], 1);
        if (half == 0) s_zrel[n]  = make_float4(zb[0], zb[1], zb[2], zb[3]);
        else           s_zroot[n] = make_float4(zb[4], zb[5], zb[6], zb[7]);
    }
    __syncthreads();

    // ---------------- Phase 3: conv2 aggregation (2-wide) + write g_act ----------------
    if (t < NPG * 2) {
        int n = t >> 1, half = t & 1;
        const float* zr = (const float*)s_zrel;
        float2 acc = *(const float2*)((const float*)(s_zroot + n) + half * 2);
        int i0 = s_start[n], i1 = s_start[n + 1];
        for (int i = i0; i < i1; i++) {
            float2 e2 = s_sedge[i];
            int s = __float_as_int(e2.y);
            float w = e2.x;
            float2 z = *(const float2*)(zr + s * 4 + half * 2);
            acc.x += w * z.x;
            acc.y += w * z.y;
        }
        *(float2*)(g_act + (size_t)g * ACTW + n * 4 + half * 2) =
            make_float2(fmaxf(acc.x, 0.f), fmaxf(acc.y, 0.f));
    }
}

// =================================================================
// K2: out = sigmoid(relu(act @ Wo1 + bo1) @ Wo2 + bo2)
// 32-row x 128-col tile per block (grid 1024 x 128 thr), 4x8 thread tile,
// double-buffered smem. ~70 regs -> ~6 CTAs/SM (vs 4 at 8x8).
// =================================================================
__global__ __launch_bounds__(128)
void k2_outmlp(const float* __restrict__ Wo1,   // [226][128]
               const float* __restrict__ bo1,   // [128]
               const float* __restrict__ Wo2,   // [128]
               const float* __restrict__ bo2,   // [1]
               float* __restrict__ out)         // [B]
{
    __shared__ __align__(16) float sA[2][KCH * 32];
    __shared__ __align__(16) float sW[2][KCH * 128];
    const int tid = threadIdx.x;
    const int tx = tid & 15, ty = tid >> 4;         // ty 0..7
    const int blockRow = blockIdx.x * 32;
    const int r0 = ty * 4, c0 = tx * 8;

    unsigned long long acc[4][4];
    #pragma unroll
    for (int r = 0; r < 4; r++)
        #pragma unroll
        for (int cp = 0; cp < 4; cp++) acc[r][cp] = 0ULL;

    const int arow = tid & 31, akq = tid >> 5;      // A: 32 rows x 4 kq
    auto load_chunk = [&](int kb, int buf) {
        const int k0 = kb * KCH;
        {
            float4 v = *(const float4*)(g_act + (size_t)(blockRow + arow) * ACTW + k0 + akq * 4);
            sA[buf][(akq * 4 + 0) * 32 + arow] = v.x;
            sA[buf][(akq * 4 + 1) * 32 + arow] = v.y;
            sA[buf][(akq * 4 + 2) * 32 + arow] = v.z;
            sA[buf][(akq * 4 + 3) * 32 + arow] = v.w;
        }
        #pragma unroll
        for (int q = 0; q < 4; q++) {                      // W: 16 k x 128 cols
            int idx = tid + q * 128;
            int kk = idx >> 5, c4 = (idx & 31) * 4;
            int k = k0 + kk;
            float4 w = (k < 226) ? *(const float4*)(Wo1 + (size_t)k * 128 + c4)
                                 : make_float4(0.f, 0.f, 0.f, 0.f);
            *(float4*)(sW[buf] + kk * 128 + c4) = w;
        }
    };

    load_chunk(0, 0);
    __syncthreads();

    for (int kb = 0; kb < 15; kb++) {
        const int cur = kb & 1;
        if (kb < 14) load_chunk(kb + 1, cur ^ 1);
        #pragma unroll
        for (int kk = 0; kk < KCH; kk++) {
            float4 a = *(const float4*)(sA[cur] + kk * 32 + r0);
            ulonglong2 wA = *(const ulonglong2*)(sW[cur] + kk * 128 + c0);
            ulonglong2 wB = *(const ulonglong2*)(sW[cur] + kk * 128 + c0 + 4);
            unsigned long long ad0 = pk2(a.x, a.x);
            unsigned long long ad1 = pk2(a.y, a.y);
            unsigned long long ad2 = pk2(a.z, a.z);
            unsigned long long ad3 = pk2(a.w, a.w);
            fma2(acc[0][0], ad0, wA.x); fma2(acc[0][1], ad0, wA.y);
            fma2(acc[0][2], ad0, wB.x); fma2(acc[0][3], ad0, wB.y);
            fma2(acc[1][0], ad1, wA.x); fma2(acc[1][1], ad1, wA.y);
            fma2(acc[1][2], ad1, wB.x); fma2(acc[1][3], ad1, wB.y);
            fma2(acc[2][0], ad2, wA.x); fma2(acc[2][1], ad2, wA.y);
            fma2(acc[2][2], ad2, wB.x); fma2(acc[2][3], ad2, wB.y);
            fma2(acc[3][0], ad3, wA.x); fma2(acc[3][1], ad3, wA.y);
            fma2(acc[3][2], ad3, wB.x); fma2(acc[3][3], ad3, wB.y);
        }
        __syncthreads();
    }

    // Epilogue: relu + dot with Wo2, reduce across 16 col-threads, sigmoid.
    float b1v[8], w2v[8];
    #pragma unroll
    for (int c = 0; c < 8; c++) { b1v[c] = bo1[c0 + c]; w2v[c] = Wo2[c0 + c]; }
    float p[4];
    #pragma unroll
    for (int r = 0; r < 4; r++) {
        p[r] = 0.f;
        #pragma unroll
        for (int cp = 0; cp < 4; cp++) {
            float2 v = upk(acc[r][cp]);
            p[r] += fmaxf(v.x + b1v[2 * cp],     0.f) * w2v[2 * cp];
            p[r] += fmaxf(v.y + b1v[2 * cp + 1], 0.f) * w2v[2 * cp + 1];
        }
    }
    #pragma unroll
    for (int r = 0; r < 4; r++) {
        #pragma unroll
        for (int off = 8; off > 0; off >>= 1)
            p[r] += __shfl_xor_sync(0xffffffffu, p[r], off, 16);
    }
    if (tx == 0) {
        float bb = bo2[0];
        #pragma unroll
        for (int r = 0; r < 4; r++) {
            float z = p[r] + bb;
            out[blockRow + r0 + r] = 1.f / (1.f + expf(-z));
        }
    }
}

extern "C" void kernel_launch(void* const* d_in, const int* in_sizes, int n_in,
                              void* d_out, int out_size)
{
    const float* x       = (const float*)d_in[0];
    const int*   ei      = (const int*)  d_in[1];
    const float* ea      = (const float*)d_in[2];
    const float* gf      = (const float*)d_in[3];
    const float* W_rel1  = (const float*)d_in[4];
    const float* b1      = (const float*)d_in[5];
    const float* W_root1 = (const float*)d_in[6];
    const float* W_rel2  = (const float*)d_in[7];
    const float* b2      = (const float*)d_in[8];
    const float* W_root2 = (const float*)d_in[9];
    const float* Wg1     = (const float*)d_in[10];
    const float* bg1     = (const float*)d_in[11];
    const float* Wg2     = (const float*)d_in[12];
    const float* bg2     = (const float*)d_in[13];
    const float* Wg3     = (const float*)d_in[14];
    const float* bg3     = (const float*)d_in[15];
    const float* Wo1     = (const float*)d_in[16];
    const float* bo1     = (const float*)d_in[17];
    const float* Wo2     = (const float*)d_in[18];
    const float* bo2     = (const float*)d_in[19];
    float* out = (float*)d_out;

    k1_graph<<<BGR, 128>>>(x, ei, ea, gf,
                           W_rel1, b1, W_root1,
                           W_rel2, b2, W_root2,
                           Wg1, bg1, Wg2, bg2, Wg3, bg3);
    k2_outmlp<<<BGR / 32, 128>>>(Wo1, bo1, Wo2, bo2, out);
}

// round 12
// speedup vs baseline: 1.1272x; 1.1272x over previous
#include <cuda_runtime.h>
#include <cuda_bf16.h>
#include <cstdint>
#include <math.h>

// Problem constants
#define BGR   32768      // graphs
#define NPG   54         // nodes per graph
#define EPG   144        // directed edges per graph
#define GLOB  10
#define ACTW  240        // padded activation width (216 embeds + 10 glob + 14 pad) = 15*16
#define KCH   16         // K-chunk for K2

// Scratch: concatenated activations [BGR][ACTW]; cols 226..239 zeroed
__device__ float g_act[(size_t)BGR * ACTW];

// ---------------- f32x2 packed helpers (sm_100+) ----------------
__device__ __forceinline__ unsigned long long pk2(float x, float y) {
    unsigned long long r;
    asm("mov.b64 %0, {%1, %2};" : "=l"(r) : "f"(x), "f"(y));
    return r;
}
__device__ __forceinline__ void fma2(unsigned long long &d, unsigned long long a, unsigned long long b) {
    asm("fma.rn.f32x2 %0, %1, %2, %0;" : "+l"(d) : "l"(a), "l"(b));
}
__device__ __forceinline__ float2 upk(unsigned long long v) {
    float2 f;
    asm("mov.b64 {%0, %1}, %2;" : "=f"(f.x), "=f"(f.y) : "l"(v));
    return f;
}

// =================================================================
// K1: per-graph fused GraphConv x2 + global MLP -> g_act
// vs R10: warp-specialized loading — each warp loads only what its P1
// section needs (latency hidden by its own scoreboard, not a block
// barrier). P2/P3 byte-identical to R10.
// =================================================================
__global__ __launch_bounds__(128)
void k1_graph(const float* __restrict__ x,
              const int*   __restrict__ ei,      // [2][E]
              const float* __restrict__ ea,      // [E]
              const float* __restrict__ gf,      // [B][10]
              const float* __restrict__ W_rel1,  // [8][16]
              const float* __restrict__ b1,      // [16]
              const float* __restrict__ W_root1, // [8][16]
              const float* __restrict__ W_rel2,  // [16][4]
              const float* __restrict__ b2,      // [4]
              const float* __restrict__ W_root2, // [16][4]
              const float* __restrict__ Wg1, const float* __restrict__ bg1,
              const float* __restrict__ Wg2, const float* __restrict__ bg2,
              const float* __restrict__ Wg3, const float* __restrict__ bg3)
{
    __shared__ float4 sx4[NPG * 2];          // x rows [54][8]
    __shared__ int    s_src[EPG], s_dst[EPG];
    __shared__ float  s_attr[EPG];
    __shared__ int    s_cnt[56], s_start[56], s_rank[EPG];
    __shared__ __align__(8) float2 s_sedge[EPG];   // sorted {attr, src_as_float}
    __shared__ __align__(8) float s_yroot[NPG * 16];   // x@W_root1 + b1
    __shared__ __align__(16) float4 s_zrel[NPG];    // h1@W_rel2
    __shared__ __align__(16) float4 s_zroot[NPG];   // h1@W_root2 + b2
    __shared__ __align__(16) float  w_rel1[128], w_root1[128], b1s[16];
    __shared__ __align__(16) float  w_rel2[64],  w_root2[64], b2s[4];
    __shared__ float  swg1[80], sbg1[8], swg2[64], sbg2[8], swg3[80], sbg3[10];
    __shared__ float  s_gf[GLOB];

    const int t    = threadIdx.x;
    const int lane = t & 31;
    const int warp = t >> 5;
    const int g    = blockIdx.x;

    const long long E = (long long)BGR * EPG;

    // ---------------- Phase 1 (fused loads + work, warp-specialized) ----------------
    if (warp == 0) {
        // --- warp0 loads ei/ea, then builds CSR ---
        {
            const int base = g * NPG;
            const int4*   sp = (const int4*)(ei + (size_t)g * EPG);
            const int4*   dp = (const int4*)(ei + E + (size_t)g * EPG);
            const float4* ap = (const float4*)(ea + (size_t)g * EPG);
            #pragma unroll
            for (int c = 0; c < 2; c++) {
                int i = c * 32 + lane;
                if (i < 36) {
                    int4 vs = sp[i];
                    s_src[i * 4 + 0] = vs.x - base;
                    s_src[i * 4 + 1] = vs.y - base;
                    s_src[i * 4 + 2] = vs.z - base;
                    s_src[i * 4 + 3] = vs.w - base;
                    int4 vd = dp[i];
                    s_dst[i * 4 + 0] = vd.x - base;
                    s_dst[i * 4 + 1] = vd.y - base;
                    s_dst[i * 4 + 2] = vd.z - base;
                    s_dst[i * 4 + 3] = vd.w - base;
                    float4 va = ap[i];
                    s_attr[i * 4 + 0] = va.x;
                    s_attr[i * 4 + 1] = va.y;
                    s_attr[i * 4 + 2] = va.z;
                    s_attr[i * 4 + 3] = va.w;
                }
            }
            for (int i = lane; i < 56; i += 32) s_cnt[i] = 0;
        }
        __syncwarp();
        #pragma unroll
        for (int c = 0; c < 5; c++) {
            int e = c * 32 + lane;
            bool valid = (e < EPG);
            int d = valid ? s_dst[e] : 54;      // sentinel bucket (unused)
            unsigned mask = __match_any_sync(0xffffffffu, d);
            int leader = __ffs(mask) - 1;
            int rk = __popc(mask & ((1u << lane) - 1u));
            int basec = s_cnt[d];
            if (valid) s_rank[e] = basec + rk;
            __syncwarp();
            if (lane == leader) s_cnt[d] = basec + __popc(mask);
            __syncwarp();
        }
        // Warp-parallel exclusive prefix scan of s_cnt[0..53] -> s_start[0..54]
        {
            int v0 = (lane < NPG) ? s_cnt[lane] : 0;
            int v1 = (lane + 32 < NPG) ? s_cnt[lane + 32] : 0;
            int s0 = v0, s1 = v1;
            #pragma unroll
            for (int off = 1; off < 32; off <<= 1) {
                int n0 = __shfl_up_sync(0xffffffffu, s0, off);
                int n1 = __shfl_up_sync(0xffffffffu, s1, off);
                if (lane >= off) { s0 += n0; s1 += n1; }
            }
            int total0 = __shfl_sync(0xffffffffu, s0, 31);
            s_start[lane] = s0 - v0;
            if (lane + 32 <= NPG) s_start[lane + 32] = total0 + s1 - v1;
        }
        __syncwarp();
        #pragma unroll
        for (int c = 0; c < 5; c++) {
            int e = c * 32 + lane;
            if (e < EPG) {
                int slot = s_start[s_dst[e]] + s_rank[e];
                s_sedge[slot] = make_float2(s_attr[e], __int_as_float(s_src[e]));
            }
        }
    } else if (warp == 3) {
        // --- warp3 loads shared weights + globals, then runs global MLP ---
        for (int i = lane; i < 128; i += 32) w_rel1[i] = W_rel1[i];
        for (int i = lane; i < 64;  i += 32) { w_rel2[i] = W_rel2[i]; w_root2[i] = W_root2[i]; }
        if (lane < 4)  b2s[lane] = b2[lane];
        for (int i = lane; i < 80;  i += 32) { swg1[i] = Wg1[i]; swg3[i] = Wg3[i]; }
        for (int i = lane; i < 64;  i += 32) swg2[i] = Wg2[i];
        if (lane < 8)  { sbg1[lane] = bg1[lane]; sbg2[lane] = bg2[lane]; }
        if (lane < 10) { sbg3[lane] = bg3[lane]; s_gf[lane] = gf[(size_t)g * GLOB + lane]; }
        __syncwarp();
        // Global MLP 10 -> 8 -> 8 -> 10 (shuffle-broadcast)
        float g1 = 0.f;
        if (lane < 8) {
            float a = sbg1[lane];
            #pragma unroll
            for (int i = 0; i < GLOB; i++) a += s_gf[i] * swg1[i * 8 + lane];
            g1 = fmaxf(a, 0.f);
        }
        float a2 = (lane < 8) ? sbg2[lane] : 0.f;
        #pragma unroll
        for (int i = 0; i < 8; i++) {
            float v = __shfl_sync(0xffffffffu, g1, i);
            if (lane < 8) a2 += v * swg2[i * 8 + lane];
        }
        float g2 = fmaxf(a2, 0.f);
        float a3 = (lane < GLOB) ? sbg3[lane] : 0.f;
        #pragma unroll
        for (int i = 0; i < 8; i++) {
            float v = __shfl_sync(0xffffffffu, g2, i);
            if (lane < GLOB) a3 += v * swg3[i * GLOB + lane];
        }
        if (lane < GLOB) g_act[(size_t)g * ACTW + 216 + lane] = fmaxf(a3, 0.f);
        if (lane >= GLOB && lane < 24) g_act[(size_t)g * ACTW + 216 + lane] = 0.f; // pad 226..239
    } else {
        // --- warps 1-2 load x + W_root1/b1, then compute y_root ---
        int idx = (warp - 1) * 32 + lane;                 // 0..63
        {
            const float4* xg = (const float4*)(x + (size_t)g * (NPG * 8));
            for (int i = idx; i < NPG * 2; i += 64) sx4[i] = xg[i];
            for (int i = idx; i < 128; i += 64) w_root1[i] = W_root1[i];
            if (idx < 16) b1s[idx] = b1[idx];
        }
        asm volatile("bar.sync 1, 64;" ::: "memory");     // warps 1+2 only
        for (int o = idx; o < NPG * 8; o += 64) {         // 432 float2 outputs
            int n = o >> 3, j = o & 7;                    // node, k-pair
            float4 X0 = sx4[n * 2], X1 = sx4[n * 2 + 1];
            float xf[8] = {X0.x, X0.y, X0.z, X0.w, X1.x, X1.y, X1.z, X1.w};
            unsigned long long acc = *(const unsigned long long*)(b1s + 2 * j);
            #pragma unroll
            for (int f = 0; f < 8; f++) {
                unsigned long long wd = *(const unsigned long long*)(w_root1 + f * 16 + 2 * j);
                fma2(acc, pk2(xf[f], xf[f]), wd);
            }
            *(float2*)(s_yroot + n * 16 + 2 * j) = upk(acc);
        }
    }
    __syncthreads();

    // ---------------- Phase 2: fused conv1 agg + h1 + z (register pair chain) ----------------
    if (t < NPG * 2) {
        const int n = t >> 1, half = t & 1;
        const unsigned mk = (t < 96) ? 0xffffffffu : 0x00000fffu;  // active lanes in my warp

        // (a) gather my 4 agg dims over this node's in-edges
        float4 agg = make_float4(0.f, 0.f, 0.f, 0.f);
        const int i0 = s_start[n], i1 = s_start[n + 1];
        for (int i = i0; i < i1; i++) {
            float2 e2 = s_sedge[i];
            int s = __float_as_int(e2.y);
            float w = e2.x;
            float4 xv = sx4[s * 2 + half];
            agg.x += w * xv.x; agg.y += w * xv.y; agg.z += w * xv.z; agg.w += w * xv.w;
        }

        // (b) pair-exchange -> full agg[8]
        float4 aggO;
        aggO.x = __shfl_xor_sync(mk, agg.x, 1);
        aggO.y = __shfl_xor_sync(mk, agg.y, 1);
        aggO.z = __shfl_xor_sync(mk, agg.z, 1);
        aggO.w = __shfl_xor_sync(mk, agg.w, 1);
        float a8[8];
        if (half == 0) {
            a8[0] = agg.x;  a8[1] = agg.y;  a8[2] = agg.z;  a8[3] = agg.w;
            a8[4] = aggO.x; a8[5] = aggO.y; a8[6] = aggO.z; a8[7] = aggO.w;
        } else {
            a8[0] = aggO.x; a8[1] = aggO.y; a8[2] = aggO.z; a8[3] = aggO.w;
            a8[4] = agg.x;  a8[5] = agg.y;  a8[6] = agg.z;  a8[7] = agg.w;
        }

        // (c) my 8 h1 outputs: k in [half*8, half*8+8); acc init = y_root (has b1)
        unsigned long long acc[4];
        #pragma unroll
        for (int j = 0; j < 4; j++)
            acc[j] = *(const unsigned long long*)(s_yroot + n * 16 + half * 8 + 2 * j);
        #pragma unroll
        for (int f = 0; f < 8; f++) {
            unsigned long long ad = pk2(a8[f], a8[f]);
            const ulonglong2* wr = (const ulonglong2*)(w_rel1 + f * 16 + half * 8);
            ulonglong2 w0 = wr[0], w1 = wr[1];
            fma2(acc[0], ad, w0.x); fma2(acc[1], ad, w0.y);
            fma2(acc[2], ad, w1.x); fma2(acc[3], ad, w1.y);
        }
        float h[8];
        #pragma unroll
        for (int j = 0; j < 4; j++) {
            float2 v = upk(acc[j]);
            h[2 * j]     = fmaxf(v.x, 0.f);
            h[2 * j + 1] = fmaxf(v.y, 0.f);
        }

        // (d) z partials over my k-half: z_rel = h1@W_rel2, z_root = h1@W_root2 (+b2 on half0)
        unsigned long long zr0 = 0ULL, zr1 = 0ULL, zo0, zo1;
        if (half == 0) {
            ulonglong2 bb = *(const ulonglong2*)b2s;
            zo0 = bb.x; zo1 = bb.y;
        } else { zo0 = 0ULL; zo1 = 0ULL; }
        #pragma unroll
        for (int kk = 0; kk < 8; kk++) {
            int k = half * 8 + kk;
            unsigned long long hd = pk2(h[kk], h[kk]);
            ulonglong2 wr = *(const ulonglong2*)(w_rel2 + k * 4);
            fma2(zr0, hd, wr.x); fma2(zr1, hd, wr.y);
            ulonglong2 wo = *(const ulonglong2*)(w_root2 + k * 4);
            fma2(zo0, hd, wo.x); fma2(zo1, hd, wo.y);
        }
        // (e) pair-combine and write z
        float2 a0 = upk(zr0), a1 = upk(zr1), b0 = upk(zo0), b1v = upk(zo1);
        float zb[8] = {a0.x, a0.y, a1.x, a1.y, b0.x, b0.y, b1v.x, b1v.y};
        #pragma unroll
        for (int j = 0; j < 8; j++)
            zb[j] += __shfl_xor_sync(mk, zb[j], 1);
        if (half == 0) s_zrel[n]  = make_float4(zb[0], zb[1], zb[2], zb[3]);
        else           s_zroot[n] = make_float4(zb[4], zb[5], zb[6], zb[7]);
    }
    __syncthreads();

    // ---------------- Phase 3: conv2 aggregation (2-wide) + write g_act ----------------
    if (t < NPG * 2) {
        int n = t >> 1, half = t & 1;
        const float* zr = (const float*)s_zrel;
        float2 acc = *(const float2*)((const float*)(s_zroot + n) + half * 2);
        int i0 = s_start[n], i1 = s_start[n + 1];
        for (int i = i0; i < i1; i++) {
            float2 e2 = s_sedge[i];
            int s = __float_as_int(e2.y);
            float w = e2.x;
            float2 z = *(const float2*)(zr + s * 4 + half * 2);
            acc.x += w * z.x;
            acc.y += w * z.y;
        }
        *(float2*)(g_act + (size_t)g * ACTW + n * 4 + half * 2) =
            make_float2(fmaxf(acc.x, 0.f), fmaxf(acc.y, 0.f));
    }
}

// =================================================================
// K2: out = sigmoid(relu(act @ Wo1 + bo1) @ Wo2 + bo2)
// 64-row x 128-col tile per block (grid 512 x 128 thr), 8x8 thread tile,
// double-buffered smem. (R10 exact — measured 59.1us)
// =================================================================
__global__ __launch_bounds__(128)
void k2_outmlp(const float* __restrict__ Wo1,   // [226][128]
               const float* __restrict__ bo1,   // [128]
               const float* __restrict__ Wo2,   // [128]
               const float* __restrict__ bo2,   // [1]
               float* __restrict__ out)         // [B]
{
    __shared__ __align__(16) float sA[2][KCH * 64];
    __shared__ __align__(16) float sW[2][KCH * 128];
    const int tid = threadIdx.x;
    const int tx = tid & 15, ty = tid >> 4;
    const int blockRow = blockIdx.x * 64;
    const int r0 = ty * 8, c0 = tx * 8;

    unsigned long long acc[8][4];
    #pragma unroll
    for (int r = 0; r < 8; r++)
        #pragma unroll
        for (int cp = 0; cp < 4; cp++) acc[r][cp] = 0ULL;

    auto load_chunk = [&](int kb, int buf) {
        const int k0 = kb * KCH;
        #pragma unroll
        for (int q = 0; q < 2; q++) {                      // A: 64 rows x 16 k
            int idx = tid + q * 128;
            int row = idx & 63, kq = idx >> 6;
            float4 v = *(const float4*)(g_act + (size_t)(blockRow + row) * ACTW + k0 + kq * 4);
            sA[buf][(kq * 4 + 0) * 64 + row] = v.x;
            sA[buf][(kq * 4 + 1) * 64 + row] = v.y;
            sA[buf][(kq * 4 + 2) * 64 + row] = v.z;
            sA[buf][(kq * 4 + 3) * 64 + row] = v.w;
        }
        #pragma unroll
        for (int q = 0; q < 4; q++) {                      // W: 16 k x 128 cols
            int idx = tid + q * 128;
            int kk = idx >> 5, c4 = (idx & 31) * 4;
            int k = k0 + kk;
            float4 w = (k < 226) ? *(const float4*)(Wo1 + (size_t)k * 128 + c4)
                                 : make_float4(0.f, 0.f, 0.f, 0.f);
            *(float4*)(sW[buf] + kk * 128 + c4) = w;
        }
    };

    load_chunk(0, 0);
    __syncthreads();

    for (int kb = 0; kb < 15; kb++) {
        const int cur = kb & 1;
        if (kb < 14) load_chunk(kb + 1, cur ^ 1);
        #pragma unroll
        for (int kk = 0; kk < KCH; kk++) {
            float4 aLo = *(const float4*)(sA[cur] + kk * 64 + r0);
            float4 aHi = *(const float4*)(sA[cur] + kk * 64 + r0 + 4);
            ulonglong2 wA = *(const ulonglong2*)(sW[cur] + kk * 128 + c0);
            ulonglong2 wB = *(const ulonglong2*)(sW[cur] + kk * 128 + c0 + 4);
            float ar[8] = {aLo.x, aLo.y, aLo.z, aLo.w, aHi.x, aHi.y, aHi.z, aHi.w};
            #pragma unroll
            for (int r = 0; r < 8; r++) {
                unsigned long long ad = pk2(ar[r], ar[r]);
                fma2(acc[r][0], ad, wA.x);
                fma2(acc[r][1], ad, wA.y);
                fma2(acc[r][2], ad, wB.x);
                fma2(acc[r][3], ad, wB.y);
            }
        }
        __syncthreads();
    }

    // Epilogue: relu + dot with Wo2, reduce across 16 col-threads, sigmoid.
    float b1v[8], w2v[8];
    #pragma unroll
    for (int c = 0; c < 8; c++) { b1v[c] = bo1[c0 + c]; w2v[c] = Wo2[c0 + c]; }
    float p[8];
    #pragma unroll
    for (int r = 0; r < 8; r++) {
        p[r] = 0.f;
        #pragma unroll
        for (int cp = 0; cp < 4; cp++) {
            float2 v = upk(acc[r][cp]);
            p[r] += fmaxf(v.x + b1v[2 * cp],     0.f) * w2v[2 * cp];
            p[r] += fmaxf(v.y + b1v[2 * cp + 1], 0.f) * w2v[2 * cp + 1];
        }
    }
    #pragma unroll
    for (int r = 0; r < 8; r++) {
        #pragma unroll
        for (int off = 8; off > 0; off >>= 1)
            p[r] += __shfl_xor_sync(0xffffffffu, p[r], off, 16);
    }
    if (tx == 0) {
        float bb = bo2[0];
        #pragma unroll
        for (int r = 0; r < 8; r++) {
            float z = p[r] + bb;
            out[blockRow + r0 + r] = 1.f / (1.f + expf(-z));
        }
    }
}

extern "C" void kernel_launch(void* const* d_in, const int* in_sizes, int n_in,
                              void* d_out, int out_size)
{
    const float* x       = (const float*)d_in[0];
    const int*   ei      = (const int*)  d_in[1];
    const float* ea      = (const float*)d_in[2];
    const float* gf      = (const float*)d_in[3];
    const float* W_rel1  = (const float*)d_in[4];
    const float* b1      = (const float*)d_in[5];
    const float* W_root1 = (const float*)d_in[6];
    const float* W_rel2  = (const float*)d_in[7];
    const float* b2      = (const float*)d_in[8];
    const float* W_root2 = (const float*)d_in[9];
    const float* Wg1     = (const float*)d_in[10];
    const float* bg1     = (const float*)d_in[11];
    const float* Wg2     = (const float*)d_in[12];
    const float* bg2     = (const float*)d_in[13];
    const float* Wg3     = (const float*)d_in[14];
    const float* bg3     = (const float*)d_in[15];
    const float* Wo1     = (const float*)d_in[16];
    const float* bo1     = (const float*)d_in[17];
    const float* Wo2     = (const float*)d_in[18];
    const float* bo2     = (const float*)d_in[19];
    float* out = (float*)d_out;

    k1_graph<<<BGR, 128>>>(x, ei, ea, gf,
                           W_rel1, b1, W_root1,
                           W_rel2, b2, W_root2,
                           Wg1, bg1, Wg2, bg2, Wg3, bg3);
    k2_outmlp<<<BGR / 64, 128>>>(Wo1, bo1, Wo2, bo2, out);
}

// round 13
// speedup vs baseline: 1.1412x; 1.0124x over previous
#include <cuda_runtime.h>
#include <cuda_bf16.h>
#include <cstdint>
#include <math.h>

// Problem constants
#define BGR   32768      // graphs
#define NPG   54         // nodes per graph
#define EPG   144        // directed edges per graph
#define GLOB  10
#define ACTW  240        // padded activation width (216 embeds + 10 glob + 14 pad) = 15*16
#define KCH   16         // K-chunk for K2

// Scratch: concatenated activations [BGR][ACTW]; cols 226..239 zeroed
__device__ float g_act[(size_t)BGR * ACTW];

// ---------------- f32x2 packed helpers (sm_100+) ----------------
__device__ __forceinline__ unsigned long long pk2(float x, float y) {
    unsigned long long r;
    asm("mov.b64 %0, {%1, %2};" : "=l"(r) : "f"(x), "f"(y));
    return r;
}
__device__ __forceinline__ void fma2(unsigned long long &d, unsigned long long a, unsigned long long b) {
    asm("fma.rn.f32x2 %0, %1, %2, %0;" : "+l"(d) : "l"(a), "l"(b));
}
__device__ __forceinline__ float2 upk(unsigned long long v) {
    float2 f;
    asm("mov.b64 {%0, %1}, %2;" : "=f"(f.x), "=f"(f.y) : "l"(v));
    return f;
}

// =================================================================
// K1: per-graph fused GraphConv x2 + global MLP -> g_act
// vs R12: unroll-2 software-pipelined gathers (P2a, P3) with float4
// two-edge loads; P2(e) shfl count 8 -> 4. Structure unchanged.
// =================================================================
__global__ __launch_bounds__(128)
void k1_graph(const float* __restrict__ x,
              const int*   __restrict__ ei,      // [2][E]
              const float* __restrict__ ea,      // [E]
              const float* __restrict__ gf,      // [B][10]
              const float* __restrict__ W_rel1,  // [8][16]
              const float* __restrict__ b1,      // [16]
              const float* __restrict__ W_root1, // [8][16]
              const float* __restrict__ W_rel2,  // [16][4]
              const float* __restrict__ b2,      // [4]
              const float* __restrict__ W_root2, // [16][4]
              const float* __restrict__ Wg1, const float* __restrict__ bg1,
              const float* __restrict__ Wg2, const float* __restrict__ bg2,
              const float* __restrict__ Wg3, const float* __restrict__ bg3)
{
    __shared__ float4 sx4[NPG * 2];          // x rows [54][8]
    __shared__ int    s_src[EPG], s_dst[EPG];
    __shared__ float  s_attr[EPG];
    __shared__ int    s_cnt[56], s_start[56], s_rank[EPG];
    __shared__ __align__(16) float2 s_sedge[EPG];   // sorted {attr, src_as_float}
    __shared__ __align__(8) float s_yroot[NPG * 16];   // x@W_root1 + b1
    __shared__ __align__(16) float4 s_zrel[NPG];    // h1@W_rel2
    __shared__ __align__(16) float4 s_zroot[NPG];   // h1@W_root2 + b2
    __shared__ __align__(16) float  w_rel1[128], w_root1[128], b1s[16];
    __shared__ __align__(16) float  w_rel2[64],  w_root2[64], b2s[4];
    __shared__ float  swg1[80], sbg1[8], swg2[64], sbg2[8], swg3[80], sbg3[10];
    __shared__ float  s_gf[GLOB];

    const int t    = threadIdx.x;
    const int lane = t & 31;
    const int warp = t >> 5;
    const int g    = blockIdx.x;

    const long long E = (long long)BGR * EPG;

    // ---------------- Phase 1 (fused loads + work, warp-specialized) ----------------
    if (warp == 0) {
        // --- warp0 loads ei/ea, then builds CSR ---
        {
            const int base = g * NPG;
            const int4*   sp = (const int4*)(ei + (size_t)g * EPG);
            const int4*   dp = (const int4*)(ei + E + (size_t)g * EPG);
            const float4* ap = (const float4*)(ea + (size_t)g * EPG);
            #pragma unroll
            for (int c = 0; c < 2; c++) {
                int i = c * 32 + lane;
                if (i < 36) {
                    int4 vs = sp[i];
                    s_src[i * 4 + 0] = vs.x - base;
                    s_src[i * 4 + 1] = vs.y - base;
                    s_src[i * 4 + 2] = vs.z - base;
                    s_src[i * 4 + 3] = vs.w - base;
                    int4 vd = dp[i];
                    s_dst[i * 4 + 0] = vd.x - base;
                    s_dst[i * 4 + 1] = vd.y - base;
                    s_dst[i * 4 + 2] = vd.z - base;
                    s_dst[i * 4 + 3] = vd.w - base;
                    float4 va = ap[i];
                    s_attr[i * 4 + 0] = va.x;
                    s_attr[i * 4 + 1] = va.y;
                    s_attr[i * 4 + 2] = va.z;
                    s_attr[i * 4 + 3] = va.w;
                }
            }
            for (int i = lane; i < 56; i += 32) s_cnt[i] = 0;
        }
        __syncwarp();
        #pragma unroll
        for (int c = 0; c < 5; c++) {
            int e = c * 32 + lane;
            bool valid = (e < EPG);
            int d = valid ? s_dst[e] : 54;      // sentinel bucket (unused)
            unsigned mask = __match_any_sync(0xffffffffu, d);
            int leader = __ffs(mask) - 1;
            int rk = __popc(mask & ((1u << lane) - 1u));
            int basec = s_cnt[d];
            if (valid) s_rank[e] = basec + rk;
            __syncwarp();
            if (lane == leader) s_cnt[d] = basec + __popc(mask);
            __syncwarp();
        }
        // Warp-parallel exclusive prefix scan of s_cnt[0..53] -> s_start[0..54]
        {
            int v0 = (lane < NPG) ? s_cnt[lane] : 0;
            int v1 = (lane + 32 < NPG) ? s_cnt[lane + 32] : 0;
            int s0 = v0, s1 = v1;
            #pragma unroll
            for (int off = 1; off < 32; off <<= 1) {
                int n0 = __shfl_up_sync(0xffffffffu, s0, off);
                int n1 = __shfl_up_sync(0xffffffffu, s1, off);
                if (lane >= off) { s0 += n0; s1 += n1; }
            }
            int total0 = __shfl_sync(0xffffffffu, s0, 31);
            s_start[lane] = s0 - v0;
            if (lane + 32 <= NPG) s_start[lane + 32] = total0 + s1 - v1;
        }
        __syncwarp();
        #pragma unroll
        for (int c = 0; c < 5; c++) {
            int e = c * 32 + lane;
            if (e < EPG) {
                int slot = s_start[s_dst[e]] + s_rank[e];
                s_sedge[slot] = make_float2(s_attr[e], __int_as_float(s_src[e]));
            }
        }
    } else if (warp == 3) {
        // --- warp3 loads shared weights + globals, then runs global MLP ---
        for (int i = lane; i < 128; i += 32) w_rel1[i] = W_rel1[i];
        for (int i = lane; i < 64;  i += 32) { w_rel2[i] = W_rel2[i]; w_root2[i] = W_root2[i]; }
        if (lane < 4)  b2s[lane] = b2[lane];
        for (int i = lane; i < 80;  i += 32) { swg1[i] = Wg1[i]; swg3[i] = Wg3[i]; }
        for (int i = lane; i < 64;  i += 32) swg2[i] = Wg2[i];
        if (lane < 8)  { sbg1[lane] = bg1[lane]; sbg2[lane] = bg2[lane]; }
        if (lane < 10) { sbg3[lane] = bg3[lane]; s_gf[lane] = gf[(size_t)g * GLOB + lane]; }
        __syncwarp();
        // Global MLP 10 -> 8 -> 8 -> 10 (shuffle-broadcast)
        float g1 = 0.f;
        if (lane < 8) {
            float a = sbg1[lane];
            #pragma unroll
            for (int i = 0; i < GLOB; i++) a += s_gf[i] * swg1[i * 8 + lane];
            g1 = fmaxf(a, 0.f);
        }
        float a2 = (lane < 8) ? sbg2[lane] : 0.f;
        #pragma unroll
        for (int i = 0; i < 8; i++) {
            float v = __shfl_sync(0xffffffffu, g1, i);
            if (lane < 8) a2 += v * swg2[i * 8 + lane];
        }
        float g2 = fmaxf(a2, 0.f);
        float a3 = (lane < GLOB) ? sbg3[lane] : 0.f;
        #pragma unroll
        for (int i = 0; i < 8; i++) {
            float v = __shfl_sync(0xffffffffu, g2, i);
            if (lane < GLOB) a3 += v * swg3[i * GLOB + lane];
        }
        if (lane < GLOB) g_act[(size_t)g * ACTW + 216 + lane] = fmaxf(a3, 0.f);
        if (lane >= GLOB && lane < 24) g_act[(size_t)g * ACTW + 216 + lane] = 0.f; // pad 226..239
    } else {
        // --- warps 1-2 load x + W_root1/b1, then compute y_root ---
        int idx = (warp - 1) * 32 + lane;                 // 0..63
        {
            const float4* xg = (const float4*)(x + (size_t)g * (NPG * 8));
            for (int i = idx; i < NPG * 2; i += 64) sx4[i] = xg[i];
            for (int i = idx; i < 128; i += 64) w_root1[i] = W_root1[i];
            if (idx < 16) b1s[idx] = b1[idx];
        }
        asm volatile("bar.sync 1, 64;" ::: "memory");     // warps 1+2 only
        for (int o = idx; o < NPG * 8; o += 64) {         // 432 float2 outputs
            int n = o >> 3, j = o & 7;                    // node, k-pair
            float4 X0 = sx4[n * 2], X1 = sx4[n * 2 + 1];
            float xf[8] = {X0.x, X0.y, X0.z, X0.w, X1.x, X1.y, X1.z, X1.w};
            unsigned long long acc = *(const unsigned long long*)(b1s + 2 * j);
            #pragma unroll
            for (int f = 0; f < 8; f++) {
                unsigned long long wd = *(const unsigned long long*)(w_root1 + f * 16 + 2 * j);
                fma2(acc, pk2(xf[f], xf[f]), wd);
            }
            *(float2*)(s_yroot + n * 16 + 2 * j) = upk(acc);
        }
    }
    __syncthreads();

    // ---------------- Phase 2: fused conv1 agg + h1 + z (register pair chain) ----------------
    if (t < NPG * 2) {
        const int n = t >> 1, half = t & 1;
        const unsigned mk = (t < 96) ? 0xffffffffu : 0x00000fffu;  // active lanes in my warp

        // (a) gather my 4 agg dims over this node's in-edges (unroll-2, float4 edge pairs)
        float4 agg  = make_float4(0.f, 0.f, 0.f, 0.f);
        float4 aggB = make_float4(0.f, 0.f, 0.f, 0.f);
        const int i0 = s_start[n], i1 = s_start[n + 1];
        int i = i0;
        if ((i & 1) && i < i1) {                    // peel to even alignment
            float2 e2 = s_sedge[i];
            int s = __float_as_int(e2.y);
            float w = e2.x;
            float4 xv = sx4[s * 2 + half];
            agg.x += w * xv.x; agg.y += w * xv.y; agg.z += w * xv.z; agg.w += w * xv.w;
            i++;
        }
        for (; i + 1 < i1; i += 2) {
            float4 ee = *(const float4*)(s_sedge + i);   // two edges, one LDS.128
            int s0 = __float_as_int(ee.y);
            int s1 = __float_as_int(ee.w);
            float4 xa = sx4[s0 * 2 + half];
            float4 xb = sx4[s1 * 2 + half];
            agg.x  += ee.x * xa.x; agg.y  += ee.x * xa.y; agg.z  += ee.x * xa.z; agg.w  += ee.x * xa.w;
            aggB.x += ee.z * xb.x; aggB.y += ee.z * xb.y; aggB.z += ee.z * xb.z; aggB.w += ee.z * xb.w;
        }
        if (i < i1) {
            float2 e2 = s_sedge[i];
            int s = __float_as_int(e2.y);
            float w = e2.x;
            float4 xv = sx4[s * 2 + half];
            agg.x += w * xv.x; agg.y += w * xv.y; agg.z += w * xv.z; agg.w += w * xv.w;
        }
        agg.x += aggB.x; agg.y += aggB.y; agg.z += aggB.z; agg.w += aggB.w;

        // (b) pair-exchange -> full agg[8]
        float4 aggO;
        aggO.x = __shfl_xor_sync(mk, agg.x, 1);
        aggO.y = __shfl_xor_sync(mk, agg.y, 1);
        aggO.z = __shfl_xor_sync(mk, agg.z, 1);
        aggO.w = __shfl_xor_sync(mk, agg.w, 1);
        float a8[8];
        if (half == 0) {
            a8[0] = agg.x;  a8[1] = agg.y;  a8[2] = agg.z;  a8[3] = agg.w;
            a8[4] = aggO.x; a8[5] = aggO.y; a8[6] = aggO.z; a8[7] = aggO.w;
        } else {
            a8[0] = aggO.x; a8[1] = aggO.y; a8[2] = aggO.z; a8[3] = aggO.w;
            a8[4] = agg.x;  a8[5] = agg.y;  a8[6] = agg.z;  a8[7] = agg.w;
        }

        // (c) my 8 h1 outputs: k in [half*8, half*8+8); acc init = y_root (has b1)
        unsigned long long acc[4];
        #pragma unroll
        for (int j = 0; j < 4; j++)
            acc[j] = *(const unsigned long long*)(s_yroot + n * 16 + half * 8 + 2 * j);
        #pragma unroll
        for (int f = 0; f < 8; f++) {
            unsigned long long ad = pk2(a8[f], a8[f]);
            const ulonglong2* wr = (const ulonglong2*)(w_rel1 + f * 16 + half * 8);
            ulonglong2 w0 = wr[0], w1 = wr[1];
            fma2(acc[0], ad, w0.x); fma2(acc[1], ad, w0.y);
            fma2(acc[2], ad, w1.x); fma2(acc[3], ad, w1.y);
        }
        float h[8];
        #pragma unroll
        for (int j = 0; j < 4; j++) {
            float2 v = upk(acc[j]);
            h[2 * j]     = fmaxf(v.x, 0.f);
            h[2 * j + 1] = fmaxf(v.y, 0.f);
        }

        // (d) z partials over my k-half: z_rel = h1@W_rel2, z_root = h1@W_root2 (+b2 on half0)
        unsigned long long zr0 = 0ULL, zr1 = 0ULL, zo0, zo1;
        if (half == 0) {
            ulonglong2 bb = *(const ulonglong2*)b2s;
            zo0 = bb.x; zo1 = bb.y;
        } else { zo0 = 0ULL; zo1 = 0ULL; }
        #pragma unroll
        for (int kk = 0; kk < 8; kk++) {
            int k = half * 8 + kk;
            unsigned long long hd = pk2(h[kk], h[kk]);
            ulonglong2 wr = *(const ulonglong2*)(w_rel2 + k * 4);
            fma2(zr0, hd, wr.x); fma2(zr1, hd, wr.y);
            ulonglong2 wo = *(const ulonglong2*)(w_root2 + k * 4);
            fma2(zo0, hd, wo.x); fma2(zo1, hd, wo.y);
        }
        // (e) pair-combine with 4 shfls: "mine" = what I write, "oth" = partner's need.
        // half0 writes z_rel (needs partner's zr partial); half1 writes z_root
        // (needs partner's zo partial, incl. b2 seeded on half0).
        float2 r0 = upk(zr0), r1 = upk(zr1), o0 = upk(zo0), o1 = upk(zo1);
        float mine[4], oth[4];
        if (half == 0) {
            mine[0] = r0.x; mine[1] = r0.y; mine[2] = r1.x; mine[3] = r1.y;
            oth[0]  = o0.x; oth[1]  = o0.y; oth[2]  = o1.x; oth[3]  = o1.y;
        } else {
            mine[0] = o0.x; mine[1] = o0.y; mine[2] = o1.x; mine[3] = o1.y;
            oth[0]  = r0.x; oth[1]  = r0.y; oth[2]  = r1.x; oth[3]  = r1.y;
        }
        #pragma unroll
        for (int j = 0; j < 4; j++)
            mine[j] += __shfl_xor_sync(mk, oth[j], 1);
        if (half == 0) s_zrel[n]  = make_float4(mine[0], mine[1], mine[2], mine[3]);
        else           s_zroot[n] = make_float4(mine[0], mine[1], mine[2], mine[3]);
    }
    __syncthreads();

    // ---------------- Phase 3: conv2 aggregation (2-wide, unroll-2) + write g_act ----------------
    if (t < NPG * 2) {
        int n = t >> 1, half = t & 1;
        const float* zr = (const float*)s_zrel;
        float2 acc  = *(const float2*)((const float*)(s_zroot + n) + half * 2);
        float2 accB = make_float2(0.f, 0.f);
        const int i0 = s_start[n], i1 = s_start[n + 1];
        int i = i0;
        if ((i & 1) && i < i1) {
            float2 e2 = s_sedge[i];
            int s = __float_as_int(e2.y);
            float w = e2.x;
            float2 z = *(const float2*)(zr + s * 4 + half * 2);
            acc.x += w * z.x; acc.y += w * z.y;
            i++;
        }
        for (; i + 1 < i1; i += 2) {
            float4 ee = *(const float4*)(s_sedge + i);
            int s0 = __float_as_int(ee.y);
            int s1 = __float_as_int(ee.w);
            float2 za = *(const float2*)(zr + s0 * 4 + half * 2);
            float2 zb = *(const float2*)(zr + s1 * 4 + half * 2);
            acc.x  += ee.x * za.x; acc.y  += ee.x * za.y;
            accB.x += ee.z * zb.x; accB.y += ee.z * zb.y;
        }
        if (i < i1) {
            float2 e2 = s_sedge[i];
            int s = __float_as_int(e2.y);
            float w = e2.x;
            float2 z = *(const float2*)(zr + s * 4 + half * 2);
            acc.x += w * z.x; acc.y += w * z.y;
        }
        acc.x += accB.x; acc.y += accB.y;
        *(float2*)(g_act + (size_t)g * ACTW + n * 4 + half * 2) =
            make_float2(fmaxf(acc.x, 0.f), fmaxf(acc.y, 0.f));
    }
}

// =================================================================
// K2: out = sigmoid(relu(act @ Wo1 + bo1) @ Wo2 + bo2)
// 64-row x 128-col tile per block (grid 512 x 128 thr), 8x8 thread tile,
// double-buffered smem. (R10 exact — measured ~59us)
// =================================================================
__global__ __launch_bounds__(128)
void k2_outmlp(const float* __restrict__ Wo1,   // [226][128]
               const float* __restrict__ bo1,   // [128]
               const float* __restrict__ Wo2,   // [128]
               const float* __restrict__ bo2,   // [1]
               float* __restrict__ out)         // [B]
{
    __shared__ __align__(16) float sA[2][KCH * 64];
    __shared__ __align__(16) float sW[2][KCH * 128];
    const int tid = threadIdx.x;
    const int tx = tid & 15, ty = tid >> 4;
    const int blockRow = blockIdx.x * 64;
    const int r0 = ty * 8, c0 = tx * 8;

    unsigned long long acc[8][4];
    #pragma unroll
    for (int r = 0; r < 8; r++)
        #pragma unroll
        for (int cp = 0; cp < 4; cp++) acc[r][cp] = 0ULL;

    auto load_chunk = [&](int kb, int buf) {
        const int k0 = kb * KCH;
        #pragma unroll
        for (int q = 0; q < 2; q++) {                      // A: 64 rows x 16 k
            int idx = tid + q * 128;
            int row = idx & 63, kq = idx >> 6;
            float4 v = *(const float4*)(g_act + (size_t)(blockRow + row) * ACTW + k0 + kq * 4);
            sA[buf][(kq * 4 + 0) * 64 + row] = v.x;
            sA[buf][(kq * 4 + 1) * 64 + row] = v.y;
            sA[buf][(kq * 4 + 2) * 64 + row] = v.z;
            sA[buf][(kq * 4 + 3) * 64 + row] = v.w;
        }
        #pragma unroll
        for (int q = 0; q < 4; q++) {                      // W: 16 k x 128 cols
            int idx = tid + q * 128;
            int kk = idx >> 5, c4 = (idx & 31) * 4;
            int k = k0 + kk;
            float4 w = (k < 226) ? *(const float4*)(Wo1 + (size_t)k * 128 + c4)
                                 : make_float4(0.f, 0.f, 0.f, 0.f);
            *(float4*)(sW[buf] + kk * 128 + c4) = w;
        }
    };

    load_chunk(0, 0);
    __syncthreads();

    for (int kb = 0; kb < 15; kb++) {
        const int cur = kb & 1;
        if (kb < 14) load_chunk(kb + 1, cur ^ 1);
        #pragma unroll
        for (int kk = 0; kk < KCH; kk++) {
            float4 aLo = *(const float4*)(sA[cur] + kk * 64 + r0);
            float4 aHi = *(const float4*)(sA[cur] + kk * 64 + r0 + 4);
            ulonglong2 wA = *(const ulonglong2*)(sW[cur] + kk * 128 + c0);
            ulonglong2 wB = *(const ulonglong2*)(sW[cur] + kk * 128 + c0 + 4);
            float ar[8] = {aLo.x, aLo.y, aLo.z, aLo.w, aHi.x, aHi.y, aHi.z, aHi.w};
            #pragma unroll
            for (int r = 0; r < 8; r++) {
                unsigned long long ad = pk2(ar[r], ar[r]);
                fma2(acc[r][0], ad, wA.x);
                fma2(acc[r][1], ad, wA.y);
                fma2(acc[r][2], ad, wB.x);
                fma2(acc[r][3], ad, wB.y);
            }
        }
        __syncthreads();
    }

    // Epilogue: relu + dot with Wo2, reduce across 16 col-threads, sigmoid.
    float b1v[8], w2v[8];
    #pragma unroll
    for (int c = 0; c < 8; c++) { b1v[c] = bo1[c0 + c]; w2v[c] = Wo2[c0 + c]; }
    float p[8];
    #pragma unroll
    for (int r = 0; r < 8; r++) {
        p[r] = 0.f;
        #pragma unroll
        for (int cp = 0; cp < 4; cp++) {
            float2 v = upk(acc[r][cp]);
            p[r] += fmaxf(v.x + b1v[2 * cp],     0.f) * w2v[2 * cp];
            p[r] += fmaxf(v.y + b1v[2 * cp + 1], 0.f) * w2v[2 * cp + 1];
        }
    }
    #pragma unroll
    for (int r = 0; r < 8; r++) {
        #pragma unroll
        for (int off = 8; off > 0; off >>= 1)
            p[r] += __shfl_xor_sync(0xffffffffu, p[r], off, 16);
    }
    if (tx == 0) {
        float bb = bo2[0];
        #pragma unroll
        for (int r = 0; r < 8; r++) {
            float z = p[r] + bb;
            out[blockRow + r0 + r] = 1.f / (1.f + expf(-z));
        }
    }
}

extern "C" void kernel_launch(void* const* d_in, const int* in_sizes, int n_in,
                              void* d_out, int out_size)
{
    const float* x       = (const float*)d_in[0];
    const int*   ei      = (const int*)  d_in[1];
    const float* ea      = (const float*)d_in[2];
    const float* gf      = (const float*)d_in[3];
    const float* W_rel1  = (const float*)d_in[4];
    const float* b1      = (const float*)d_in[5];
    const float* W_root1 = (const float*)d_in[6];
    const float* W_rel2  = (const float*)d_in[7];
    const float* b2      = (const float*)d_in[8];
    const float* W_root2 = (const float*)d_in[9];
    const float* Wg1     = (const float*)d_in[10];
    const float* bg1     = (const float*)d_in[11];
    const float* Wg2     = (const float*)d_in[12];
    const float* bg2     = (const float*)d_in[13];
    const float* Wg3     = (const float*)d_in[14];
    const float* bg3     = (const float*)d_in[15];
    const float* Wo1     = (const float*)d_in[16];
    const float* bo1     = (const float*)d_in[17];
    const float* Wo2     = (const float*)d_in[18];
    const float* bo2     = (const float*)d_in[19];
    float* out = (float*)d_out;

    k1_graph<<<BGR, 128>>>(x, ei, ea, gf,
                           W_rel1, b1, W_root1,
                           W_rel2, b2, W_root2,
                           Wg1, bg1, Wg2, bg2, Wg3, bg3);
    k2_outmlp<<<BGR / 64, 128>>>(Wo1, bo1, Wo2, bo2, out);
}